// round 13
// baseline (speedup 1.0000x reference)
#include <cuda_runtime.h>
#include <cuda_bf16.h>

#define INPUT   128
#define HIDDEN  1024
#define OUTPUT  128
#define BATCH   256
#define TSTEPS  512

// ---------------------------- device globals -------------------------------
__device__ float g_beff[HIDDEN];
__device__ float g_b1[HIDDEN];
// bf16 split planes of h_t for every t: [t][hh=0/hl=1][m][k]
__device__ __align__(16) __nv_bfloat16 g_Hs[TSTEPS][2][BATCH][HIDDEN];
// bf16 split of W_eff, transposed (n-major): [Wh=0/Wl=1][n][k]
__device__ __align__(16) __nv_bfloat16 g_BT[2][HIDDEN][HIDDEN];
// bf16 split of W_h2o, transposed (n-major): [Wh=0/Wl=1][n][k]
__device__ __align__(16) __nv_bfloat16 g_BTo[2][OUTPUT][HIDDEN];

// ---------------------------- PTX helpers ----------------------------------
__device__ __forceinline__ unsigned smem_u32(const void* p) {
    unsigned a;
    asm("{ .reg .u64 t; cvta.to.shared.u64 t, %1; cvt.u32.u64 %0, t; }"
        : "=r"(a) : "l"(p));
    return a;
}
__device__ __forceinline__ void cp16(unsigned s, const void* g) {
    asm volatile("cp.async.cg.shared.global [%0], [%1], 16;"
                 :: "r"(s), "l"(g) : "memory");
}
__device__ __forceinline__ void cp_commit() {
    asm volatile("cp.async.commit_group;" ::: "memory");
}
__device__ __forceinline__ void ldm4(unsigned* r, unsigned addr) {
    asm volatile("ldmatrix.sync.aligned.m8n8.x4.shared.b16 {%0,%1,%2,%3}, [%4];"
                 : "=r"(r[0]), "=r"(r[1]), "=r"(r[2]), "=r"(r[3]) : "r"(addr));
}
__device__ __forceinline__ void mma16816(float* d, const unsigned* a,
                                         const unsigned* b) {
    asm volatile(
        "mma.sync.aligned.m16n8k16.row.col.f32.bf16.bf16.f32 "
        "{%0,%1,%2,%3}, {%4,%5,%6,%7}, {%8,%9}, {%0,%1,%2,%3};"
        : "+f"(d[0]), "+f"(d[1]), "+f"(d[2]), "+f"(d[3])
        : "r"(a[0]), "r"(a[1]), "r"(a[2]), "r"(a[3]), "r"(b[0]), "r"(b[1]));
}

// ===========================================================================
// Step kernel: h_t = tanh(h_{t-1} @ W_eff + b_eff)
//   3-pass bf16 split: hh@Wh + hl@Wh + hh@Wl  (hl@Wl dropped, ~2^-18)
// grid (16 ntile, 8 mtile), 256 threads. CTA tile 32x64, warp tile 16x16.
// BK=64 stages, 3 slots, 2 in flight, one sync/stage (16 syncs/step).
// smem 81KB: AH/AL[3][32][72], BH/BL[3][64][72] bf16 (72-pad = conflict-free).
// ===========================================================================
#define S_APAD   72
#define S_ASLOT  (32 * S_APAD)              // 2304 elems
#define S_BSLOT  (64 * S_APAD)              // 4608 elems
#define S_AH     0
#define S_AL     (3 * S_ASLOT)
#define S_BH     (6 * S_ASLOT)
#define S_BL     (S_BH + 3 * S_BSLOT)
#define S_TOT_E  (S_BH + 6 * S_BSLOT)       // 41472 elems = 82944 B
#define S_NST    16                          // k64 stages

__global__ void __launch_bounds__(256, 1) rnn_step_hmma(int t) {
    extern __shared__ __align__(16) __nv_bfloat16 dyn[];

    const int tid = threadIdx.x, wid = tid >> 5, l = tid & 31;
    const int nBase = blockIdx.x * 64, mBase = blockIdx.y * 32;

    const __nv_bfloat16* gAh = &g_Hs[t - 1][0][mBase][0];
    const __nv_bfloat16* gAl = &g_Hs[t - 1][1][mBase][0];
    const __nv_bfloat16* gBh = &g_BT[0][nBase][0];
    const __nv_bfloat16* gBl = &g_BT[1][nBase][0];

    auto load_stage = [&](int slot, int st) {
        const int k0 = st * 64;
#pragma unroll
        for (int i = 0; i < 2; ++i) {        // A: 512 cp16
            int c = tid + i * 256;
            int part = c >> 8, r = (c & 255) >> 3, s = (c & 7) * 8;
            __nv_bfloat16* d = dyn + (part ? S_AL : S_AH) + slot * S_ASLOT
                               + r * S_APAD + s;
            const __nv_bfloat16* src = (part ? gAl : gAh) + r * HIDDEN + k0 + s;
            cp16(smem_u32(d), src);
        }
#pragma unroll
        for (int i = 0; i < 4; ++i) {        // B: 1024 cp16
            int c = tid + i * 256;
            int part = c >> 9, r = (c & 511) >> 3, s = (c & 7) * 8;
            __nv_bfloat16* d = dyn + (part ? S_BL : S_BH) + slot * S_BSLOT
                               + r * S_APAD + s;
            const __nv_bfloat16* src = (part ? gBl : gBh) + r * HIDDEN + k0 + s;
            cp16(smem_u32(d), src);
        }
    };

    // ldmatrix lane offsets (bytes within a slot)
    const int rowA = ((wid >> 2) << 4) + (l & 15);
    const unsigned offA = (unsigned)(rowA * S_APAD + ((l >> 4) << 3)) * 2;
    const int rowB = ((wid & 3) << 4) + (l & 7) + ((l >> 4) << 3);
    const unsigned offB = (unsigned)(rowB * S_APAD + (((l >> 3) & 1) << 3)) * 2;

    const unsigned uAh = smem_u32(dyn + S_AH) + offA;
    const unsigned uAl = smem_u32(dyn + S_AL) + offA;
    const unsigned uBh = smem_u32(dyn + S_BH) + offB;
    const unsigned uBl = smem_u32(dyn + S_BL) + offB;

    float acc0[4] = {0.f, 0.f, 0.f, 0.f};
    float acc1[4] = {0.f, 0.f, 0.f, 0.f};

    load_stage(0, 0); cp_commit();
    load_stage(1, 1); cp_commit();

    for (int st = 0; st < S_NST; ++st) {
        asm volatile("cp.async.wait_group 1;" ::: "memory");
        __syncthreads();                       // stage st ready; slot st-1 free
        if (st + 2 < S_NST) load_stage((st + 2) % 3, st + 2);
        cp_commit();

        const int slot = st % 3;
        const unsigned aH = uAh + (unsigned)(slot * S_ASLOT) * 2;
        const unsigned aL = uAl + (unsigned)(slot * S_ASLOT) * 2;
        const unsigned bH = uBh + (unsigned)(slot * S_BSLOT) * 2;
        const unsigned bL = uBl + (unsigned)(slot * S_BSLOT) * 2;

#pragma unroll
        for (int kj = 0; kj < 4; ++kj) {       // 4 x k16 per stage
            unsigned Ah[4], Al[4], Bh[4], Bl[4];
            ldm4(Ah, aH + kj * 32);
            ldm4(Al, aL + kj * 32);
            ldm4(Bh, bH + kj * 32);
            ldm4(Bl, bL + kj * 32);
            mma16816(acc0, Ah, Bh);
            mma16816(acc1, Ah, Bh + 2);
            mma16816(acc0, Al, Bh);
            mma16816(acc1, Al, Bh + 2);
            mma16816(acc0, Ah, Bl);
            mma16816(acc1, Ah, Bl + 2);
        }
    }
    asm volatile("cp.async.wait_group 0;" ::: "memory");

    // epilogue: bias + tanh; write bf16 split planes for step t
    const int g = l >> 2, tq = l & 3;
    const int m0 = mBase + ((wid >> 2) << 4);
    const int n0 = nBase + ((wid & 3) << 4);
#pragma unroll
    for (int half = 0; half < 2; ++half) {
        const int m = m0 + g + half * 8;
#pragma unroll
        for (int j = 0; j < 2; ++j) {
            const float* acc = j ? acc1 : acc0;
            const int n = n0 + j * 8 + 2 * tq;
            float v0 = tanhf(acc[2 * half]     + g_beff[n]);
            float v1 = tanhf(acc[2 * half + 1] + g_beff[n + 1]);
            __nv_bfloat16 h0 = __float2bfloat16(v0);
            __nv_bfloat16 h1 = __float2bfloat16(v1);
            __nv_bfloat162 hh; hh.x = h0; hh.y = h1;
            __nv_bfloat162 hl;
            hl.x = __float2bfloat16(v0 - __bfloat162float(h0));
            hl.y = __float2bfloat16(v1 - __bfloat162float(h1));
            *(__nv_bfloat162*)&g_Hs[t][0][m][n] = hh;
            *(__nv_bfloat162*)&g_Hs[t][1][m][n] = hl;
        }
    }
}

// ===========================================================================
// out_proj on HMMA: out[t] = h_t @ W_h2o + b_h2o for t=1..511.
// CTA tile 128x64 (warps 4m x 2n, warp tile 32x32). BK=32, 3 slots,
// 2 in flight, 32 syncs. smem 92KB (40-pad, conflict-free).
// ===========================================================================
#define O_APAD   40
#define O_ASLOT  (128 * O_APAD)             // 5120 elems
#define O_BSLOT  (64 * O_APAD)              // 2560 elems
#define O_AH     0
#define O_AL     (3 * O_ASLOT)
#define O_BH     (6 * O_ASLOT)
#define O_BL     (O_BH + 3 * O_BSLOT)
#define O_TOT_E  (O_BH + 6 * O_BSLOT)       // 46080 elems = 92160 B
#define O_NST    32

__global__ void __launch_bounds__(256, 1)
out_proj_hmma(const float* __restrict__ bh2o, float* __restrict__ out) {
    extern __shared__ __align__(16) __nv_bfloat16 dyn[];

    const int tid = threadIdx.x, wid = tid >> 5, l = tid & 31;
    const int nBase = blockIdx.x * 64;
    const int rBase = blockIdx.y * 128;          // global C row base
    const int t = rBase / 256 + 1;               // one t per CTA (128 | 256)
    const int mloc = rBase & 255;

    const __nv_bfloat16* gAh = &g_Hs[t][0][mloc][0];
    const __nv_bfloat16* gAl = &g_Hs[t][1][mloc][0];
    const __nv_bfloat16* gBh = &g_BTo[0][nBase][0];
    const __nv_bfloat16* gBl = &g_BTo[1][nBase][0];

    auto load_stage = [&](int slot, int st) {
        const int k0 = st * 32;
#pragma unroll
        for (int i = 0; i < 4; ++i) {        // A: 1024 cp16
            int c = tid + i * 256;
            int part = c >> 9, r = (c & 511) >> 2, s = (c & 3) * 8;
            __nv_bfloat16* d = dyn + (part ? O_AL : O_AH) + slot * O_ASLOT
                               + r * O_APAD + s;
            const __nv_bfloat16* src = (part ? gAl : gAh) + r * HIDDEN + k0 + s;
            cp16(smem_u32(d), src);
        }
#pragma unroll
        for (int i = 0; i < 2; ++i) {        // B: 512 cp16
            int c = tid + i * 256;
            int part = c >> 8, r = (c & 255) >> 2, s = (c & 3) * 8;
            __nv_bfloat16* d = dyn + (part ? O_BL : O_BH) + slot * O_BSLOT
                               + r * O_APAD + s;
            const __nv_bfloat16* src = (part ? gBl : gBh) + r * HIDDEN + k0 + s;
            cp16(smem_u32(d), src);
        }
    };

    const int warpM = (wid >> 1) << 5;           // 0,32,64,96
    const int warpN = (wid & 1) << 5;            // 0,32
    const int rowA = warpM + (l & 15);
    const unsigned offA = (unsigned)(rowA * O_APAD + ((l >> 4) << 3)) * 2;
    const int rowB = warpN + (l & 7) + ((l >> 4) << 3);
    const unsigned offB = (unsigned)(rowB * O_APAD + (((l >> 3) & 1) << 3)) * 2;
    const unsigned mStride = (unsigned)(16 * O_APAD) * 2;   // +16 rows
    const unsigned uAh = smem_u32(dyn + O_AH) + offA;
    const unsigned uAl = smem_u32(dyn + O_AL) + offA;
    const unsigned uBh = smem_u32(dyn + O_BH) + offB;
    const unsigned uBl = smem_u32(dyn + O_BL) + offB;

    float acc[2][4][4];
#pragma unroll
    for (int a = 0; a < 2; ++a)
#pragma unroll
        for (int b = 0; b < 4; ++b)
#pragma unroll
            for (int c = 0; c < 4; ++c) acc[a][b][c] = 0.f;

    load_stage(0, 0); cp_commit();
    load_stage(1, 1); cp_commit();

    for (int st = 0; st < O_NST; ++st) {
        asm volatile("cp.async.wait_group 1;" ::: "memory");
        __syncthreads();
        if (st + 2 < O_NST) load_stage((st + 2) % 3, st + 2);
        cp_commit();

        const int slot = st % 3;
        const unsigned aHb = uAh + (unsigned)(slot * O_ASLOT) * 2;
        const unsigned aLb = uAl + (unsigned)(slot * O_ASLOT) * 2;
        const unsigned bHb = uBh + (unsigned)(slot * O_BSLOT) * 2;
        const unsigned bLb = uBl + (unsigned)(slot * O_BSLOT) * 2;

#pragma unroll
        for (int kj = 0; kj < 2; ++kj) {         // 2 x k16 per stage
            unsigned Ah[2][4], Al[2][4], Bh[8], Bl[8];
            ldm4(Ah[0], aHb + kj * 32);
            ldm4(Ah[1], aHb + kj * 32 + mStride);
            ldm4(Al[0], aLb + kj * 32);
            ldm4(Al[1], aLb + kj * 32 + mStride);
            ldm4(Bh,     bHb + kj * 32);
            ldm4(Bh + 4, bHb + kj * 32 + mStride);
            ldm4(Bl,     bLb + kj * 32);
            ldm4(Bl + 4, bLb + kj * 32 + mStride);

#pragma unroll
            for (int mi = 0; mi < 2; ++mi)
#pragma unroll
                for (int nj = 0; nj < 4; ++nj) {
                    mma16816(acc[mi][nj], Ah[mi], Bh + nj * 2);
                    mma16816(acc[mi][nj], Al[mi], Bh + nj * 2);
                    mma16816(acc[mi][nj], Ah[mi], Bl + nj * 2);
                }
        }
    }
    asm volatile("cp.async.wait_group 0;" ::: "memory");

    // epilogue: bias + fp32 store (out[0]=x0 occupies rows 0..255)
    const int g = l >> 2, tq = l & 3;
    float* outBase = out + (size_t)(256 + rBase) * OUTPUT;
#pragma unroll
    for (int mi = 0; mi < 2; ++mi)
#pragma unroll
        for (int nj = 0; nj < 4; ++nj) {
            const int n = nBase + warpN + nj * 8 + 2 * tq;
            const float b0 = bh2o[n], b1 = bh2o[n + 1];
#pragma unroll
            for (int half = 0; half < 2; ++half) {
                const int r = warpM + mi * 16 + g + half * 8;
                *(float2*)&outBase[(size_t)r * OUTPUT + n] =
                    make_float2(acc[mi][nj][2 * half] + b0,
                                acc[mi][nj][2 * half + 1] + b1);
            }
        }
}

// ===========================================================================
// fp32 FFMA2 GEMM for rnn_first (K=128): writes bf16 split planes directly.
// ===========================================================================
__device__ __forceinline__ unsigned long long pack2(float lo, float hi) {
    unsigned long long r;
    asm("mov.b64 %0, {%1, %2};" : "=l"(r) : "f"(lo), "f"(hi));
    return r;
}
__device__ __forceinline__ void unpack2(unsigned long long v, float& lo, float& hi) {
    asm("mov.b64 {%0, %1}, %2;" : "=f"(lo), "=f"(hi) : "l"(v));
}
__device__ __forceinline__ void ffma2(unsigned long long& d,
                                      unsigned long long a, unsigned long long b) {
    asm("fma.rn.f32x2 %0, %1, %2, %0;" : "+l"(d) : "l"(a), "l"(b));
}

__global__ void rnn_first(const float* __restrict__ x0,
                          const float* __restrict__ Wi2h) {
    __shared__ unsigned long long Asd[2][16][34];
    __shared__ float Bs[2][16][68];

    const int tid = threadIdx.x;
    const int tx = tid & 15, ty = tid >> 4;
    const int rowBase = blockIdx.y * 32;
    const int colBase = blockIdx.x * 64;
    const int am = tid >> 3, ak = (tid & 7) * 2;
    const int bk = tid >> 4, bn = (tid & 15) * 4;

    const float* Aptr = &x0[(size_t)(rowBase + am) * INPUT + ak];
    const float* Bptr = &Wi2h[(size_t)bk * HIDDEN + colBase + bn];

    unsigned long long acc[2][2];
    acc[0][0] = acc[0][1] = acc[1][0] = acc[1][1] = 0ull;

    float2 rA = *(const float2*)Aptr;
    float4 rB = *(const float4*)Bptr;

    const int nT = INPUT >> 4;
    for (int tt = 0; tt < nT; ++tt) {
        const int buf = tt & 1;
        Asd[buf][ak][am]     = pack2(rA.x, rA.x);
        Asd[buf][ak + 1][am] = pack2(rA.y, rA.y);
        *(float4*)&Bs[buf][bk][bn] = rB;
        __syncthreads();
        if (tt + 1 < nT) {
            rA = *(const float2*)(Aptr + (tt + 1) * 16);
            rB = *(const float4*)(Bptr + (size_t)(tt + 1) * 16 * HIDDEN);
        }
#pragma unroll
        for (int kk = 0; kk < 16; ++kk) {
            ulonglong2 ap = *(const ulonglong2*)&Asd[buf][kk][2 * ty];
            ulonglong2 bp = *(const ulonglong2*)&Bs[buf][kk][4 * tx];
            ffma2(acc[0][0], ap.x, bp.x);
            ffma2(acc[0][1], ap.x, bp.y);
            ffma2(acc[1][0], ap.y, bp.x);
            ffma2(acc[1][1], ap.y, bp.y);
        }
    }

    float4 bv = *(const float4*)&g_b1[colBase + 4 * tx];
    float o[2][4];
#pragma unroll
    for (int r = 0; r < 2; ++r) {
        unpack2(acc[r][0], o[r][0], o[r][1]);
        unpack2(acc[r][1], o[r][2], o[r][3]);
        o[r][0] += bv.x; o[r][1] += bv.y; o[r][2] += bv.z; o[r][3] += bv.w;
        const int m = rowBase + 2 * ty + r;
        const int n = colBase + 4 * tx;
#pragma unroll
        for (int c = 0; c < 4; ++c) {
            float v = tanhf(o[r][c]);
            __nv_bfloat16 h = __float2bfloat16(v);
            g_Hs[1][0][m][n + c] = h;
            g_Hs[1][1][m][n + c] = __float2bfloat16(v - __bfloat162float(h));
        }
    }
}

// ---------------------------- prep kernels ---------------------------------
__global__ void prep_weff(const float* __restrict__ Wh2h,
                          const float* __restrict__ Wh2o,
                          const float* __restrict__ Wi2h) {
    int idx = blockIdx.x * blockDim.x + threadIdx.x;
    int k = idx >> 10, j = idx & 1023;
    float s = Wh2h[idx];
    const float* wo = &Wh2o[k * OUTPUT];
#pragma unroll 8
    for (int i = 0; i < OUTPUT; ++i)
        s += wo[i] * Wi2h[i * HIDDEN + j];
    __nv_bfloat16 wh = __float2bfloat16(s);
    g_BT[0][j][k] = wh;
    g_BT[1][j][k] = __float2bfloat16(s - __bfloat162float(wh));
}

__global__ void prep_bo(const float* __restrict__ Wh2o) {
    int idx = blockIdx.x * blockDim.x + threadIdx.x;   // HIDDEN*OUTPUT
    int k = idx >> 7, n = idx & 127;
    float w = Wh2o[k * OUTPUT + n];
    __nv_bfloat16 wh = __float2bfloat16(w);
    g_BTo[0][n][k] = wh;
    g_BTo[1][n][k] = __float2bfloat16(w - __bfloat162float(wh));
}

__global__ void prep_bias(const float* __restrict__ bi2h,
                          const float* __restrict__ bh2h,
                          const float* __restrict__ bh2o,
                          const float* __restrict__ Wi2h) {
    int j = blockIdx.x * blockDim.x + threadIdx.x;
    if (j >= HIDDEN) return;
    float base = bi2h[j] + bh2h[j];
    g_b1[j] = base;
    float s = base;
#pragma unroll 8
    for (int i = 0; i < OUTPUT; ++i)
        s += bh2o[i] * Wi2h[i * HIDDEN + j];
    g_beff[j] = s;
}

// ---------------------------- launcher -------------------------------------
extern "C" void kernel_launch(void* const* d_in, const int* in_sizes, int n_in,
                              void* d_out, int out_size) {
    const float* x0   = (const float*)d_in[0];
    const float* Wi2h = (const float*)d_in[1];
    const float* bi2h = (const float*)d_in[2];
    const float* Wh2h = (const float*)d_in[3];
    const float* bh2h = (const float*)d_in[4];
    const float* Wh2o = (const float*)d_in[5];
    const float* bh2o = (const float*)d_in[6];
    float* out = (float*)d_out;

    cudaFuncSetAttribute(rnn_step_hmma,
                         cudaFuncAttributeMaxDynamicSharedMemorySize,
                         S_TOT_E * 2);
    cudaFuncSetAttribute(out_proj_hmma,
                         cudaFuncAttributeMaxDynamicSharedMemorySize,
                         O_TOT_E * 2);

    prep_weff<<<(HIDDEN * HIDDEN) / 256, 256>>>(Wh2h, Wh2o, Wi2h);
    prep_bo<<<(HIDDEN * OUTPUT) / 256, 256>>>(Wh2o);
    prep_bias<<<(HIDDEN + 255) / 256, 256>>>(bi2h, bh2h, bh2o, Wi2h);
    cudaMemcpyAsync(out, x0, BATCH * OUTPUT * sizeof(float),
                    cudaMemcpyDeviceToDevice, 0);

    rnn_first<<<dim3(HIDDEN / 64, BATCH / 32), 256>>>(x0, Wi2h);

    for (int t = 2; t < TSTEPS; ++t)
        rnn_step_hmma<<<dim3(16, 8), 256, S_TOT_E * 2>>>(t);

    out_proj_hmma<<<dim3(OUTPUT / 64, (TSTEPS - 1) * BATCH / 128), 256,
                    O_TOT_E * 2>>>(bh2o, out);
}

// round 14
// speedup vs baseline: 1.2119x; 1.2119x over previous
#include <cuda_runtime.h>
#include <cuda_bf16.h>

#define INPUT   128
#define HIDDEN  1024
#define OUTPUT  128
#define BATCH   256
#define TSTEPS  512

// ---------------------------- device globals -------------------------------
__device__ float g_beff[HIDDEN];
__device__ float g_b1[HIDDEN];
// bf16 split planes of h_t for every t: [t][hh=0/hl=1][m][k]
__device__ __align__(16) __nv_bfloat16 g_Hs[TSTEPS][2][BATCH][HIDDEN];
// bf16 split of W_eff, transposed (n-major): [Wh=0/Wl=1][n][k]
__device__ __align__(16) __nv_bfloat16 g_BT[2][HIDDEN][HIDDEN];
// bf16 split of W_h2o, transposed (n-major): [Wh=0/Wl=1][n][k]
__device__ __align__(16) __nv_bfloat16 g_BTo[2][OUTPUT][HIDDEN];

// ---------------------------- PTX helpers ----------------------------------
__device__ __forceinline__ unsigned smem_u32(const void* p) {
    unsigned a;
    asm("{ .reg .u64 t; cvta.to.shared.u64 t, %1; cvt.u32.u64 %0, t; }"
        : "=r"(a) : "l"(p));
    return a;
}
__device__ __forceinline__ void cp16(unsigned s, const void* g) {
    asm volatile("cp.async.cg.shared.global [%0], [%1], 16;"
                 :: "r"(s), "l"(g) : "memory");
}
__device__ __forceinline__ void cp_commit() {
    asm volatile("cp.async.commit_group;" ::: "memory");
}
__device__ __forceinline__ void ldm4(unsigned* r, unsigned addr) {
    asm volatile("ldmatrix.sync.aligned.m8n8.x4.shared.b16 {%0,%1,%2,%3}, [%4];"
                 : "=r"(r[0]), "=r"(r[1]), "=r"(r[2]), "=r"(r[3]) : "r"(addr));
}
__device__ __forceinline__ void mma16816(float* d, const unsigned* a,
                                         const unsigned* b) {
    asm volatile(
        "mma.sync.aligned.m16n8k16.row.col.f32.bf16.bf16.f32 "
        "{%0,%1,%2,%3}, {%4,%5,%6,%7}, {%8,%9}, {%0,%1,%2,%3};"
        : "+f"(d[0]), "+f"(d[1]), "+f"(d[2]), "+f"(d[3])
        : "r"(a[0]), "r"(a[1]), "r"(a[2]), "r"(a[3]), "r"(b[0]), "r"(b[1]));
}

// ===========================================================================
// Fused launch: CTAs [0, nStep) compute h_t = tanh(h_{t-1} @ W_eff + b_eff);
// CTAs [nStep, nStep+16) compute out[t-1] = h_{t-1} @ W_h2o + b_h2o.
// Both modes: CTA tile 32x64, warp tile 16x16 (8 warps 2m x 4n), K=1024,
// 3-pass bf16 split (hh@Wh + hl@Wh + hh@Wl; hl@Wl dropped ~2^-18).
// Pipeline: BK=32 stages, 5 slots, 4 in flight, one sync/stage (32 syncs).
// smem 75KB: AH/AL[5][32][40], BH/BL[5][64][40] bf16.
// ===========================================================================
#define S_APAD   40
#define S_ASLOT  (32 * S_APAD)              // 1280 elems
#define S_BSLOT  (64 * S_APAD)              // 2560 elems
#define S_AH     0
#define S_AL     (5 * S_ASLOT)              // 6400
#define S_BH     (10 * S_ASLOT)             // 12800
#define S_BL     (S_BH + 5 * S_BSLOT)       // 25600
#define S_TOT_E  (S_BH + 10 * S_BSLOT)      // 38400 elems = 76800 B
#define S_NST    32                          // k32 stages

__global__ void __launch_bounds__(256, 1)
rnn_fused(int t, int nStep, const float* __restrict__ bh2o,
          float* __restrict__ out) {
    extern __shared__ __align__(16) __nv_bfloat16 dyn[];

    const int tid = threadIdx.x, wid = tid >> 5, l = tid & 31;
    const bool stepMode = (int)blockIdx.x < nStep;
    const int bx = stepMode ? blockIdx.x : blockIdx.x - nStep;

    int nBase, mBase;
    const __nv_bfloat16 *gBh, *gBl;
    if (stepMode) {
        nBase = (bx & 15) * 64;  mBase = (bx >> 4) * 32;
        gBh = &g_BT[0][nBase][0];  gBl = &g_BT[1][nBase][0];
    } else {
        nBase = (bx & 1) * 64;   mBase = (bx >> 1) * 32;
        gBh = &g_BTo[0][nBase][0]; gBl = &g_BTo[1][nBase][0];
    }
    const __nv_bfloat16* gAh = &g_Hs[t - 1][0][mBase][0];
    const __nv_bfloat16* gAl = &g_Hs[t - 1][1][mBase][0];

    auto load_stage = [&](int slot, int st) {
        const int k0 = st * 32;
        {   // A: 2 parts x 32 rows x 4 segs = 256 cp16 -> 1/thread
            int c = tid;
            int part = c >> 7, r = (c & 127) >> 2, s = (c & 3) * 8;
            __nv_bfloat16* d = dyn + (part ? S_AL : S_AH) + slot * S_ASLOT
                               + r * S_APAD + s;
            cp16(smem_u32(d), (part ? gAl : gAh) + r * HIDDEN + k0 + s);
        }
#pragma unroll
        for (int i = 0; i < 2; ++i) {   // B: 2 parts x 64 rows x 4 segs = 512
            int c = tid + i * 256;
            int part = c >> 8, r = (c & 255) >> 2, s = (c & 3) * 8;
            __nv_bfloat16* d = dyn + (part ? S_BL : S_BH) + slot * S_BSLOT
                               + r * S_APAD + s;
            cp16(smem_u32(d), (part ? gBl : gBh) + r * HIDDEN + k0 + s);
        }
    };

    // ldmatrix lane offsets (bytes within a slot)
    const int rowA = ((wid >> 2) << 4) + (l & 15);
    const unsigned offA = (unsigned)(rowA * S_APAD + ((l >> 4) << 3)) * 2;
    const int rowB = ((wid & 3) << 4) + (l & 7) + ((l >> 4) << 3);
    const unsigned offB = (unsigned)(rowB * S_APAD + (((l >> 3) & 1) << 3)) * 2;

    const unsigned uAh = smem_u32(dyn + S_AH) + offA;
    const unsigned uAl = smem_u32(dyn + S_AL) + offA;
    const unsigned uBh = smem_u32(dyn + S_BH) + offB;
    const unsigned uBl = smem_u32(dyn + S_BL) + offB;

    float acc0[4] = {0.f, 0.f, 0.f, 0.f};
    float acc1[4] = {0.f, 0.f, 0.f, 0.f};

    load_stage(0, 0); cp_commit();
    load_stage(1, 1); cp_commit();
    load_stage(2, 2); cp_commit();
    load_stage(3, 3); cp_commit();

    for (int st = 0; st < S_NST; ++st) {
        asm volatile("cp.async.wait_group 3;" ::: "memory");
        __syncthreads();                  // stage st ready; slot st-1 free
        if (st + 4 < S_NST) load_stage((st + 4) % 5, st + 4);
        cp_commit();

        const int slot = st % 5;
        const unsigned aH = uAh + (unsigned)(slot * S_ASLOT) * 2;
        const unsigned aL = uAl + (unsigned)(slot * S_ASLOT) * 2;
        const unsigned bH = uBh + (unsigned)(slot * S_BSLOT) * 2;
        const unsigned bL = uBl + (unsigned)(slot * S_BSLOT) * 2;

#pragma unroll
        for (int kj = 0; kj < 2; ++kj) {  // 2 x k16 per stage
            unsigned Ah[4], Al[4], Bh[4], Bl[4];
            ldm4(Ah, aH + kj * 32);
            ldm4(Al, aL + kj * 32);
            ldm4(Bh, bH + kj * 32);
            ldm4(Bl, bL + kj * 32);
            mma16816(acc0, Ah, Bh);
            mma16816(acc1, Ah, Bh + 2);
            mma16816(acc0, Al, Bh);
            mma16816(acc1, Al, Bh + 2);
            mma16816(acc0, Ah, Bl);
            mma16816(acc1, Ah, Bl + 2);
        }
    }
    asm volatile("cp.async.wait_group 0;" ::: "memory");

    // ---- epilogues ----
    const int g = l >> 2, tq = l & 3;
    const int m0 = (wid >> 2) << 4;
    const int n0 = (wid & 3) << 4;

    if (stepMode) {
        // bias + tanh; write bf16 split planes for step t
#pragma unroll
        for (int half = 0; half < 2; ++half) {
            const int m = mBase + m0 + g + half * 8;
#pragma unroll
            for (int j = 0; j < 2; ++j) {
                const float* acc = j ? acc1 : acc0;
                const int n = nBase + n0 + j * 8 + 2 * tq;
                float v0 = tanhf(acc[2 * half]     + g_beff[n]);
                float v1 = tanhf(acc[2 * half + 1] + g_beff[n + 1]);
                __nv_bfloat16 h0 = __float2bfloat16(v0);
                __nv_bfloat16 h1 = __float2bfloat16(v1);
                __nv_bfloat162 hh; hh.x = h0; hh.y = h1;
                __nv_bfloat162 hl;
                hl.x = __float2bfloat16(v0 - __bfloat162float(h0));
                hl.y = __float2bfloat16(v1 - __bfloat162float(h1));
                *(__nv_bfloat162*)&g_Hs[t][0][m][n] = hh;
                *(__nv_bfloat162*)&g_Hs[t][1][m][n] = hl;
            }
        }
    } else {
        // out[t-1] rows (t-1)*256 + m; bias + fp32 store
#pragma unroll
        for (int half = 0; half < 2; ++half) {
            const int m = mBase + m0 + g + half * 8;
            float* rowp = out + ((size_t)(t - 1) * 256 + m) * OUTPUT;
#pragma unroll
            for (int j = 0; j < 2; ++j) {
                const float* acc = j ? acc1 : acc0;
                const int n = nBase + n0 + j * 8 + 2 * tq;
                *(float2*)&rowp[n] =
                    make_float2(acc[2 * half]     + bh2o[n],
                                acc[2 * half + 1] + bh2o[n + 1]);
            }
        }
    }
}

// ===========================================================================
// fp32 FFMA2 GEMM for rnn_first (K=128): writes bf16 split planes directly.
// ===========================================================================
__device__ __forceinline__ unsigned long long pack2(float lo, float hi) {
    unsigned long long r;
    asm("mov.b64 %0, {%1, %2};" : "=l"(r) : "f"(lo), "f"(hi));
    return r;
}
__device__ __forceinline__ void unpack2(unsigned long long v, float& lo, float& hi) {
    asm("mov.b64 {%0, %1}, %2;" : "=f"(lo), "=f"(hi) : "l"(v));
}
__device__ __forceinline__ void ffma2(unsigned long long& d,
                                      unsigned long long a, unsigned long long b) {
    asm("fma.rn.f32x2 %0, %1, %2, %0;" : "+l"(d) : "l"(a), "l"(b));
}

__global__ void rnn_first(const float* __restrict__ x0,
                          const float* __restrict__ Wi2h) {
    __shared__ unsigned long long Asd[2][16][34];
    __shared__ float Bs[2][16][68];

    const int tid = threadIdx.x;
    const int tx = tid & 15, ty = tid >> 4;
    const int rowBase = blockIdx.y * 32;
    const int colBase = blockIdx.x * 64;
    const int am = tid >> 3, ak = (tid & 7) * 2;
    const int bk = tid >> 4, bn = (tid & 15) * 4;

    const float* Aptr = &x0[(size_t)(rowBase + am) * INPUT + ak];
    const float* Bptr = &Wi2h[(size_t)bk * HIDDEN + colBase + bn];

    unsigned long long acc[2][2];
    acc[0][0] = acc[0][1] = acc[1][0] = acc[1][1] = 0ull;

    float2 rA = *(const float2*)Aptr;
    float4 rB = *(const float4*)Bptr;

    const int nT = INPUT >> 4;
    for (int tt = 0; tt < nT; ++tt) {
        const int buf = tt & 1;
        Asd[buf][ak][am]     = pack2(rA.x, rA.x);
        Asd[buf][ak + 1][am] = pack2(rA.y, rA.y);
        *(float4*)&Bs[buf][bk][bn] = rB;
        __syncthreads();
        if (tt + 1 < nT) {
            rA = *(const float2*)(Aptr + (tt + 1) * 16);
            rB = *(const float4*)(Bptr + (size_t)(tt + 1) * 16 * HIDDEN);
        }
#pragma unroll
        for (int kk = 0; kk < 16; ++kk) {
            ulonglong2 ap = *(const ulonglong2*)&Asd[buf][kk][2 * ty];
            ulonglong2 bp = *(const ulonglong2*)&Bs[buf][kk][4 * tx];
            ffma2(acc[0][0], ap.x, bp.x);
            ffma2(acc[0][1], ap.x, bp.y);
            ffma2(acc[1][0], ap.y, bp.x);
            ffma2(acc[1][1], ap.y, bp.y);
        }
    }

    float4 bv = *(const float4*)&g_b1[colBase + 4 * tx];
    float o[2][4];
#pragma unroll
    for (int r = 0; r < 2; ++r) {
        unpack2(acc[r][0], o[r][0], o[r][1]);
        unpack2(acc[r][1], o[r][2], o[r][3]);
        o[r][0] += bv.x; o[r][1] += bv.y; o[r][2] += bv.z; o[r][3] += bv.w;
        const int m = rowBase + 2 * ty + r;
        const int n = colBase + 4 * tx;
#pragma unroll
        for (int c = 0; c < 4; ++c) {
            float v = tanhf(o[r][c]);
            __nv_bfloat16 h = __float2bfloat16(v);
            g_Hs[1][0][m][n + c] = h;
            g_Hs[1][1][m][n + c] = __float2bfloat16(v - __bfloat162float(h));
        }
    }
}

// ---------------------------- prep kernels ---------------------------------
__global__ void prep_weff(const float* __restrict__ Wh2h,
                          const float* __restrict__ Wh2o,
                          const float* __restrict__ Wi2h) {
    int idx = blockIdx.x * blockDim.x + threadIdx.x;
    int k = idx >> 10, j = idx & 1023;
    float s = Wh2h[idx];
    const float* wo = &Wh2o[k * OUTPUT];
#pragma unroll 8
    for (int i = 0; i < OUTPUT; ++i)
        s += wo[i] * Wi2h[i * HIDDEN + j];
    __nv_bfloat16 wh = __float2bfloat16(s);
    g_BT[0][j][k] = wh;
    g_BT[1][j][k] = __float2bfloat16(s - __bfloat162float(wh));
}

__global__ void prep_bo(const float* __restrict__ Wh2o) {
    int idx = blockIdx.x * blockDim.x + threadIdx.x;   // HIDDEN*OUTPUT
    int k = idx >> 7, n = idx & 127;
    float w = Wh2o[k * OUTPUT + n];
    __nv_bfloat16 wh = __float2bfloat16(w);
    g_BTo[0][n][k] = wh;
    g_BTo[1][n][k] = __float2bfloat16(w - __bfloat162float(wh));
}

__global__ void prep_bias(const float* __restrict__ bi2h,
                          const float* __restrict__ bh2h,
                          const float* __restrict__ bh2o,
                          const float* __restrict__ Wi2h) {
    int j = blockIdx.x * blockDim.x + threadIdx.x;
    if (j >= HIDDEN) return;
    float base = bi2h[j] + bh2h[j];
    g_b1[j] = base;
    float s = base;
#pragma unroll 8
    for (int i = 0; i < OUTPUT; ++i)
        s += bh2o[i] * Wi2h[i * HIDDEN + j];
    g_beff[j] = s;
}

// ---------------------------- launcher -------------------------------------
extern "C" void kernel_launch(void* const* d_in, const int* in_sizes, int n_in,
                              void* d_out, int out_size) {
    const float* x0   = (const float*)d_in[0];
    const float* Wi2h = (const float*)d_in[1];
    const float* bi2h = (const float*)d_in[2];
    const float* Wh2h = (const float*)d_in[3];
    const float* bh2h = (const float*)d_in[4];
    const float* Wh2o = (const float*)d_in[5];
    const float* bh2o = (const float*)d_in[6];
    float* out = (float*)d_out;

    cudaFuncSetAttribute(rnn_fused,
                         cudaFuncAttributeMaxDynamicSharedMemorySize,
                         S_TOT_E * 2);

    prep_weff<<<(HIDDEN * HIDDEN) / 256, 256>>>(Wh2h, Wh2o, Wi2h);
    prep_bo<<<(HIDDEN * OUTPUT) / 256, 256>>>(Wh2o);
    prep_bias<<<(HIDDEN + 255) / 256, 256>>>(bi2h, bh2h, bh2o, Wi2h);
    cudaMemcpyAsync(out, x0, BATCH * OUTPUT * sizeof(float),
                    cudaMemcpyDeviceToDevice, 0);

    rnn_first<<<dim3(HIDDEN / 64, BATCH / 32), 256>>>(x0, Wi2h);

    // steps 2..511: 128 step CTAs + 16 out CTAs (for out[t-1]) per launch
    for (int t = 2; t < TSTEPS; ++t)
        rnn_fused<<<144, 256, S_TOT_E * 2>>>(t, 128, bh2o, out);

    // final: out[511] only (16 CTAs, no step work)
    rnn_fused<<<16, 256, S_TOT_E * 2>>>(TSTEPS, 0, bh2o, out);
}